// round 6
// baseline (speedup 1.0000x reference)
#include <cuda_runtime.h>
#include <cuda_bf16.h>

// ---------------------------------------------------------------------------
// QCNNHybrid R5:
//  k_statsfold : cp.async.bulk (UBLKCP) pulls 16KB/block into SMEM (bypasses
//                per-warp LDG L1 path), reduce from SMEM; last block (ticket)
//                folds BN into layer-1 and writes duplicated f32x2 params.
//  k_main      : 1 pack (2 rows)/thread, launch_bounds(128,4) -> 16 warps/SM,
//                weight pairs via aligned LDS.128.
// ---------------------------------------------------------------------------

#define NBLK_STATS 2048
#define NT_STATS   256
#define ROWS_PER_BLK 512            // 512 rows * 32B = 16KB per block
#define NT_MAIN    128

__device__ float g_partials[NBLK_STATS * 16];
__device__ unsigned int g_ticket;

// layout B (u64 units): per layer [bias x DOUT][weights j-major: DOUT x DIN]
#define FM_B 0
#define FM_W 16     // 16 + 128 = 144
#define C1_B 144
#define C1_W 160    // + 256 = 416
#define P1_B 416
#define P1_W 428    // + 192 = 620
#define C2_B 620
#define C2_W 628    // + 96 = 724
#define P2_B 724
#define P2_W 728    // + 32 = 760
#define C3_B 760
#define C3_W 764    // + 16 = 780
#define R_B  780
#define R_W  784    // + 16 = 800
#define H_B  800
#define H_W  801    // + 4 = 805
#define U_TOTAL 805
__device__ float2 g_w[U_TOTAL];

typedef unsigned long long u64;

// ------------------------------- f32x2 helpers -----------------------------
__device__ __forceinline__ u64 pk2(float a, float b) {
    u64 r;
    asm("mov.b64 %0,{%1,%2};" : "=l"(r) : "f"(a), "f"(b));
    return r;
}
__device__ __forceinline__ void upk2(u64 v, float& a, float& b) {
    asm("mov.b64 {%0,%1},%2;" : "=f"(a), "=f"(b) : "l"(v));
}
__device__ __forceinline__ u64 ffma2(u64 a, u64 b, u64 c) {
    u64 d;
    asm("fma.rn.f32x2 %0,%1,%2,%3;" : "=l"(d) : "l"(a), "l"(b), "l"(c));
    return d;
}
__device__ __forceinline__ u64 fadd2(u64 a, u64 b) {
    u64 d;
    asm("add.rn.f32x2 %0,%1,%2;" : "=l"(d) : "l"(a), "l"(b));
    return d;
}
__device__ __forceinline__ float tanh_ap(float x) {
    float y;
    asm("tanh.approx.f32 %0,%1;" : "=f"(y) : "f"(x));
    return y;
}
__device__ __forceinline__ u64 tanh2(u64 v) {
    float a, b;
    upk2(v, a, b);
    return pk2(tanh_ap(a), tanh_ap(b));
}
__device__ __forceinline__ u64 relu2(u64 v) {
    float a, b;
    upk2(v, a, b);
    return pk2(fmaxf(a, 0.0f), fmaxf(b, 0.0f));
}

// dense layer on ONE f32x2 pack (2 rows); weight pairs via aligned LDS.128.
template <int DIN, int DOUT, int BB, int WB, bool ACT>
__device__ __forceinline__ void layer1P(const u64* __restrict__ sw,
                                        const u64* __restrict__ a,
                                        u64* __restrict__ o) {
#pragma unroll
    for (int j = 0; j < DOUT; j++) {
        u64 acc = sw[BB + j];                         // duplicated bias
#pragma unroll
        for (int i = 0; i < DIN; i += 2) {
            ulonglong2 w = *(const ulonglong2*)(sw + WB + j * DIN + i);
            acc = ffma2(a[i], w.x, acc);
            acc = ffma2(a[i + 1], w.y, acc);
        }
        if (ACT) acc = tanh2(acc);
        o[j] = acc;
    }
}

// --------------------------- kernel A: stats + fold ------------------------
__global__ void __launch_bounds__(NT_STATS) k_statsfold(
    const float* __restrict__ x,
    const float* __restrict__ bn_g, const float* __restrict__ bn_b,
    const float* __restrict__ w_fm, const float* __restrict__ b_fm,
    const float* __restrict__ w_c1, const float* __restrict__ b_c1,
    const float* __restrict__ w_p1, const float* __restrict__ b_p1,
    const float* __restrict__ w_c2, const float* __restrict__ b_c2,
    const float* __restrict__ w_p2, const float* __restrict__ b_p2,
    const float* __restrict__ w_c3, const float* __restrict__ b_c3,
    const float* __restrict__ w_r,  const float* __restrict__ b_r,
    const float* __restrict__ w_h,  const float* __restrict__ b_h,
    float invB, int nrows) {
    __shared__ __align__(16) float s_buf[ROWS_PER_BLK * 8];   // 16 KB
    __shared__ __align__(8) unsigned long long s_mbar;
    int tid = threadIdx.x;

    // ---- bulk-async copy 16KB of x into SMEM ----
    unsigned int mbar_addr;
    {
        unsigned long long tmp;
        asm("{ .reg .u64 t; cvta.to.shared.u64 t, %1; mov.b64 %0, t; }"
            : "=l"(tmp) : "l"(&s_mbar));
        mbar_addr = (unsigned int)tmp;
    }
    unsigned int smem_addr;
    {
        unsigned long long tmp;
        asm("{ .reg .u64 t; cvta.to.shared.u64 t, %1; mov.b64 %0, t; }"
            : "=l"(tmp) : "l"(s_buf));
        smem_addr = (unsigned int)tmp;
    }
    const unsigned int CHUNK = ROWS_PER_BLK * 8 * 4;  // 16384 bytes
    if (tid == 0) {
        asm volatile("mbarrier.init.shared.b64 [%0], 1;" :: "r"(mbar_addr) : "memory");
        asm volatile("fence.proxy.async.shared::cta;" ::: "memory");
        asm volatile("mbarrier.arrive.expect_tx.shared.b64 _, [%0], %1;"
                     :: "r"(mbar_addr), "r"(CHUNK) : "memory");
        const char* src = (const char*)x + (size_t)blockIdx.x * CHUNK;
        asm volatile(
            "cp.async.bulk.shared::cluster.global.mbarrier::complete_tx::bytes "
            "[%0], [%1], %2, [%3];"
            :: "r"(smem_addr), "l"(src), "r"(CHUNK), "r"(mbar_addr) : "memory");
    }
    __syncthreads();
    // wait phase 0
    {
        asm volatile(
            "{\n\t"
            ".reg .pred p;\n\t"
            "WAITL_%=:\n\t"
            "mbarrier.try_wait.parity.acquire.cta.shared::cta.b64 p, [%0], 0;\n\t"
            "@!p bra WAITL_%=;\n\t"
            "}"
            :: "r"(mbar_addr) : "memory");
    }

    // ---- reduce 2 rows/thread from SMEM ----
    float s[8], q[8];
    {
        const float4* sv = (const float4*)(s_buf + tid * 16);  // 2 rows = 4 float4
        float4 a0 = sv[0], b0 = sv[1], a1 = sv[2], b1 = sv[3];
        s[0] = a0.x + a1.x; q[0] = fmaf(a0.x, a0.x, a1.x * a1.x);
        s[1] = a0.y + a1.y; q[1] = fmaf(a0.y, a0.y, a1.y * a1.y);
        s[2] = a0.z + a1.z; q[2] = fmaf(a0.z, a0.z, a1.z * a1.z);
        s[3] = a0.w + a1.w; q[3] = fmaf(a0.w, a0.w, a1.w * a1.w);
        s[4] = b0.x + b1.x; q[4] = fmaf(b0.x, b0.x, b1.x * b1.x);
        s[5] = b0.y + b1.y; q[5] = fmaf(b0.y, b0.y, b1.y * b1.y);
        s[6] = b0.z + b1.z; q[6] = fmaf(b0.z, b0.z, b1.z * b1.z);
        s[7] = b0.w + b1.w; q[7] = fmaf(b0.w, b0.w, b1.w * b1.w);
    }
#pragma unroll
    for (int c = 0; c < 8; c++) {
#pragma unroll
        for (int o = 16; o > 0; o >>= 1) {
            s[c] += __shfl_xor_sync(0xffffffffu, s[c], o);
            q[c] += __shfl_xor_sync(0xffffffffu, q[c], o);
        }
    }
    __shared__ float sm[8][16];
    int warp = tid >> 5, lane = tid & 31;
    if (lane == 0) {
#pragma unroll
        for (int c = 0; c < 8; c++) { sm[warp][c] = s[c]; sm[warp][8 + c] = q[c]; }
    }
    __syncthreads();
    if (tid < 16) {
        float acc = 0.0f;
#pragma unroll
        for (int w = 0; w < 8; w++) acc += sm[w][tid];
        g_partials[blockIdx.x * 16 + tid] = acc;
    }

    // ---- ticket: last block folds ----
    __shared__ unsigned int s_last;
    __threadfence();
    if (tid == 0) s_last = (atomicAdd(&g_ticket, 1u) == (unsigned)(gridDim.x - 1));
    __syncthreads();
    if (!s_last) return;

    __shared__ float s1[256];
    __shared__ float totals[16];
    __shared__ float scale[8], shift[8];
    {   // 16 cols x 16 chunks of 128, 8 independent accumulators per thread
        int col = tid & 15, chunk = tid >> 4;
        const float* p = g_partials + (chunk * 128) * 16 + col;
        float a0 = 0, a1 = 0, a2 = 0, a3 = 0, a4 = 0, a5 = 0, a6 = 0, a7 = 0;
#pragma unroll 4
        for (int b = 0; b < 128; b += 8) {
            a0 += p[(b + 0) * 16]; a1 += p[(b + 1) * 16];
            a2 += p[(b + 2) * 16]; a3 += p[(b + 3) * 16];
            a4 += p[(b + 4) * 16]; a5 += p[(b + 5) * 16];
            a6 += p[(b + 6) * 16]; a7 += p[(b + 7) * 16];
        }
        s1[col * 16 + chunk] = ((a0 + a1) + (a2 + a3)) + ((a4 + a5) + (a6 + a7));
    }
    __syncthreads();
    if (tid < 16) {
        float acc = 0.0f;
#pragma unroll
        for (int k = 0; k < 16; k++) acc += s1[tid * 16 + k];
        totals[tid] = acc;
    }
    __syncthreads();
    if (tid < 8) {
        float mu = totals[tid] * invB;
        float var = totals[8 + tid] * invB - mu * mu;
        float sc = bn_g[tid] * rsqrtf(var + 1e-5f);
        scale[tid] = sc;
        shift[tid] = bn_b[tid] - mu * sc;
    }
    __syncthreads();

    // folded first layer, layout B
    if (tid < 16) {
        float v = b_fm[tid];
#pragma unroll
        for (int i = 0; i < 8; i++) v += shift[i] * w_fm[i * 16 + tid];
        g_w[FM_B + tid] = make_float2(v, v);
    }
    if (tid < 128) {                                  // j = tid>>3, i = tid&7
        int j = tid >> 3, i = tid & 7;
        float v = scale[i] * w_fm[i * 16 + j];
        g_w[FM_W + j * 8 + i] = make_float2(v, v);
    }
    // generic layers: weights j-major
    for (int idx = tid; idx < 256; idx += NT_STATS) { // c1 16->16
        int j = idx >> 4, i = idx & 15;
        float v = w_c1[i * 16 + j];
        g_w[C1_W + j * 16 + i] = make_float2(v, v);
    }
    if (tid < 16) { float v = b_c1[tid]; g_w[C1_B + tid] = make_float2(v, v); }
    for (int idx = tid; idx < 192; idx += NT_STATS) { // p1 16->12
        int j = idx >> 4, i = idx & 15;
        float v = w_p1[i * 12 + j];
        g_w[P1_W + j * 16 + i] = make_float2(v, v);
    }
    if (tid < 12) { float v = b_p1[tid]; g_w[P1_B + tid] = make_float2(v, v); }
    if (tid < 96) {                                    // c2 12->8
        int j = tid / 12, i = tid % 12;
        float v = w_c2[i * 8 + j];
        g_w[C2_W + j * 12 + i] = make_float2(v, v);
    }
    if (tid < 8) { float v = b_c2[tid]; g_w[C2_B + tid] = make_float2(v, v); }
    if (tid < 32) {                                    // p2 8->4
        int j = tid >> 3, i = tid & 7;
        float v = w_p2[i * 4 + j];
        g_w[P2_W + j * 8 + i] = make_float2(v, v);
    }
    if (tid < 4) { float v = b_p2[tid]; g_w[P2_B + tid] = make_float2(v, v); }
    if (tid < 16) {                                    // c3 4->4
        int j = tid >> 2, i = tid & 3;
        float v = w_c3[i * 4 + j];
        g_w[C3_W + j * 4 + i] = make_float2(v, v);
    }
    if (tid < 4) { float v = b_c3[tid]; g_w[C3_B + tid] = make_float2(v, v); }
    if (tid < 16) {                                    // r 4->4
        int j = tid >> 2, i = tid & 3;
        float v = w_r[i * 4 + j];
        g_w[R_W + j * 4 + i] = make_float2(v, v);
    }
    if (tid < 4) { float v = b_r[tid]; g_w[R_B + tid] = make_float2(v, v); }
    if (tid < 4) { float v = w_h[tid]; g_w[H_W + tid] = make_float2(v, v); }
    if (tid == 0) { float v = b_h[0]; g_w[H_B] = make_float2(v, v); }
    __syncthreads();
    if (tid == 0) g_ticket = 0;                       // reset for next replay
}

// ------------------------------- kernel B: main ----------------------------
__global__ void __launch_bounds__(NT_MAIN, 4) k_main(const float* __restrict__ x,
                                                     float* __restrict__ out,
                                                     int nrows) {
    __shared__ __align__(16) u64 sw[U_TOTAL + 1];
    {
        const u64* gw = (const u64*)g_w;
        for (int i = threadIdx.x; i < U_TOTAL; i += NT_MAIN) sw[i] = gw[i];
    }
    __syncthreads();

    int t = blockIdx.x * NT_MAIN + threadIdx.x;
    long base = (long)t * 2;                          // 2 rows / thread
    if (base >= nrows) return;

    const float4* xv = (const float4*)(x + base * 8);
    float4 r0a = xv[0], r0b = xv[1];
    float4 r1a = xv[2], r1b = xv[3];

    u64 A[16], B[16];
    A[0] = pk2(r0a.x, r1a.x);
    A[1] = pk2(r0a.y, r1a.y);
    A[2] = pk2(r0a.z, r1a.z);
    A[3] = pk2(r0a.w, r1a.w);
    A[4] = pk2(r0b.x, r1b.x);
    A[5] = pk2(r0b.y, r1b.y);
    A[6] = pk2(r0b.z, r1b.z);
    A[7] = pk2(r0b.w, r1b.w);

    layer1P<8, 16, FM_B, FM_W, true>(sw, A, B);   // feature_map (BN folded)
    layer1P<16, 16, C1_B, C1_W, true>(sw, B, A);  // conv1
    layer1P<16, 12, P1_B, P1_W, true>(sw, A, B);  // pool1
    layer1P<12, 8, C2_B, C2_W, true>(sw, B, A);   // conv2
    layer1P<8, 4, P2_B, P2_W, true>(sw, A, B);    // pool2
    layer1P<4, 4, C3_B, C3_W, true>(sw, B, A);    // conv3 -> A[0..3]
    layer1P<4, 4, R_B, R_W, false>(sw, A, B);     // residual pre-relu
#pragma unroll
    for (int j = 0; j < 4; j++) A[j] = fadd2(A[j], relu2(B[j]));

    // head [4->1], sigmoid(z) = 0.5*tanh(0.5z)+0.5
    u64 acc = sw[H_B];
#pragma unroll
    for (int i = 0; i < 4; i++) acc = ffma2(A[i], sw[H_W + i], acc);
    float z0, z1;
    upk2(acc, z0, z1);
    float2 o;
    o.x = fmaf(0.5f, tanh_ap(0.5f * z0), 0.5f);
    o.y = fmaf(0.5f, tanh_ap(0.5f * z1), 0.5f);
    ((float2*)out)[t] = o;
}

// ------------------------------- launch ------------------------------------
extern "C" void kernel_launch(void* const* d_in, const int* in_sizes, int n_in,
                              void* d_out, int out_size) {
    const float* x    = (const float*)d_in[0];
    const float* bn_g = (const float*)d_in[1];
    const float* bn_b = (const float*)d_in[2];
    const float* w_fm = (const float*)d_in[3];
    const float* b_fm = (const float*)d_in[4];
    const float* w_c1 = (const float*)d_in[5];
    const float* b_c1 = (const float*)d_in[6];
    const float* w_p1 = (const float*)d_in[7];
    const float* b_p1 = (const float*)d_in[8];
    const float* w_c2 = (const float*)d_in[9];
    const float* b_c2 = (const float*)d_in[10];
    const float* w_p2 = (const float*)d_in[11];
    const float* b_p2 = (const float*)d_in[12];
    const float* w_c3 = (const float*)d_in[13];
    const float* b_c3 = (const float*)d_in[14];
    const float* w_r  = (const float*)d_in[15];
    const float* b_r  = (const float*)d_in[16];
    const float* w_h  = (const float*)d_in[17];
    const float* b_h  = (const float*)d_in[18];
    float* out = (float*)d_out;

    int nrows = in_sizes[0] / 8;                      // 1048576

    k_statsfold<<<NBLK_STATS, NT_STATS>>>(x, bn_g, bn_b, w_fm, b_fm,
                                          w_c1, b_c1, w_p1, b_p1, w_c2, b_c2,
                                          w_p2, b_p2, w_c3, b_c3, w_r, b_r,
                                          w_h, b_h, 1.0f / (float)nrows, nrows);
    k_main<<<(nrows / 2) / NT_MAIN, NT_MAIN>>>(x, out, nrows);
}